// round 13
// baseline (speedup 1.0000x reference)
#include <cuda_runtime.h>
#include <cuda_bf16.h>
#include <cstdint>

#define SEQ 4096
#define NB 4
#define DHD 64
#define BM 64
#define BN 64
#define NSPLIT 2
#define TILES_PER_SPLIT (SEQ / BN / NSPLIT)   // 32
#define NTHREADS 128

// bf16 copies of K and V (filled by prepass kernel). 2 MB each.
__device__ __nv_bfloat16 g_kbf[(size_t)NB * SEQ * DHD];
__device__ __nv_bfloat16 g_vbf[(size_t)NB * SEQ * DHD];
// split-KV partials: unnormalized O and row sums l, per split.
__device__ float g_opart[(size_t)NSPLIT * NB * SEQ * DHD];   // 8 MB
__device__ float g_lpart[(size_t)NSPLIT * NB * SEQ];         // 128 KB

// smem layout (bytes): Q[64][64]bf16 swizzled (8KB) | {K,V} x 2 buffers (16KB each)
#define SM_Q 0
#define SM_KV(buf) (8192 + (buf) * 16384)   // K at +0 (8KB), V at +8192 (8KB)
#define SM_TOTAL (8192 + 2 * 16384)         // 40960

// XOR swizzle inside a 128B row: 16B-chunk column ^ (row & 7)
#define SWZ(rowbyte, colbyte) ((rowbyte) + ((colbyte) ^ (((rowbyte) >> 7 & 7) << 4)))

// ---------------- helpers ----------------
__device__ __forceinline__ uint32_t smem_u32(const void* p) {
    uint32_t a;
    asm("{ .reg .u64 t; cvta.to.shared.u64 t, %1; cvt.u32.u64 %0, t; }" : "=r"(a) : "l"(p));
    return a;
}
__device__ __forceinline__ uint32_t pk_bf16x2(float lo, float hi) {
    uint32_t r;
    asm("cvt.rn.bf16x2.f32 %0, %1, %2;" : "=r"(r) : "f"(hi), "f"(lo));
    return r;
}
__device__ __forceinline__ float ex2f(float x) {
    float r; asm("ex2.approx.ftz.f32 %0, %1;" : "=f"(r) : "f"(x)); return r;
}
__device__ __forceinline__ void cpasync16(uint32_t dst, const void* src) {
    asm volatile("cp.async.cg.shared.global [%0], [%1], 16;" :: "r"(dst), "l"(src) : "memory");
}
#define CP_COMMIT() asm volatile("cp.async.commit_group;" ::: "memory")

__device__ __forceinline__ void ldm_x4(uint32_t* r, uint32_t a) {
    asm volatile("ldmatrix.sync.aligned.m8n8.x4.shared.b16 {%0,%1,%2,%3}, [%4];"
        : "=r"(r[0]), "=r"(r[1]), "=r"(r[2]), "=r"(r[3]) : "r"(a));
}
__device__ __forceinline__ void ldm_x4t(uint32_t* r, uint32_t a) {
    asm volatile("ldmatrix.sync.aligned.m8n8.x4.trans.shared.b16 {%0,%1,%2,%3}, [%4];"
        : "=r"(r[0]), "=r"(r[1]), "=r"(r[2]), "=r"(r[3]) : "r"(a));
}
__device__ __forceinline__ void mma16816(float* d, const uint32_t* a, uint32_t b0, uint32_t b1) {
    asm volatile("mma.sync.aligned.m16n8k16.row.col.f32.bf16.bf16.f32 "
        "{%0,%1,%2,%3}, {%4,%5,%6,%7}, {%8,%9}, {%0,%1,%2,%3};"
        : "+f"(d[0]), "+f"(d[1]), "+f"(d[2]), "+f"(d[3])
        : "r"(a[0]), "r"(a[1]), "r"(a[2]), "r"(a[3]), "r"(b0), "r"(b1));
}

// ---------------- prepass: fp32 -> bf16 for K and V ----------------
__global__ __launch_bounds__(256)
void cvt_kv(const float4* __restrict__ k, const float4* __restrict__ v)
{
    size_t i = (size_t)blockIdx.x * blockDim.x + threadIdx.x;   // over N/4
    float4 a = k[i];
    ((uint2*)g_kbf)[i] = make_uint2(pk_bf16x2(a.x, a.y), pk_bf16x2(a.z, a.w));
    float4 b = v[i];
    ((uint2*)g_vbf)[i] = make_uint2(pk_bf16x2(b.x, b.y), pk_bf16x2(b.z, b.w));
}

// ---------------- main kernel: split-KV partial attention ----------------
__global__ __launch_bounds__(NTHREADS, 4)
void attn_mma(const float* __restrict__ q, const int* __restrict__ scale_raw)
{
    extern __shared__ char smc[];
    const uint32_t smb = smem_u32(smc);
    const int t = threadIdx.x;
    const int wid = t >> 5;
    const int lane = t & 31;
    const int b = blockIdx.y;
    const int q0 = blockIdx.x * BM;
    const int split = blockIdx.z;
    const int t0 = split * TILES_PER_SPLIT;

    int raw = *scale_raw;
    float inv_scale = (raw >= 0 && raw < (1 << 23)) ? (float)raw : __int_as_float(raw);
    const float qf = 1.4426950408889634f / inv_scale;   // fold 1/scale and log2(e)

    const float* qb = q + ((size_t)b * SEQ + q0) * DHD;
    const __nv_bfloat16* kb = g_kbf + (size_t)b * SEQ * DHD;
    const __nv_bfloat16* vb = g_vbf + (size_t)b * SEQ * DHD;

    // ---- stage Q (bf16, prescaled, swizzled): 64 rows x 64 cols ----
    {
        const int r = t >> 1, h = t & 1;
        const float4* src = (const float4*)(qb + (size_t)r * DHD + h * 32);
        #pragma unroll
        for (int c = 0; c < 4; c++) {
            float4 x0 = src[2 * c], x1 = src[2 * c + 1];
            uint32_t p0 = pk_bf16x2(x0.x * qf, x0.y * qf);
            uint32_t p1 = pk_bf16x2(x0.z * qf, x0.w * qf);
            uint32_t p2 = pk_bf16x2(x1.x * qf, x1.y * qf);
            uint32_t p3 = pk_bf16x2(x1.z * qf, x1.w * qf);
            uint32_t a = smb + SM_Q + SWZ(r * 128, h * 64 + c * 16);
            asm volatile("st.shared.v4.b32 [%0], {%1,%2,%3,%4};"
                :: "r"(a), "r"(p0), "r"(p1), "r"(p2), "r"(p3) : "memory");
        }
    }

    // ---- K/V tile prefetch (512 x 16B chunks per tensor, 128 threads x 4) ----
    #define PREFETCH(tile, buf) do { \
        const __nv_bfloat16* ks = kb + (size_t)(tile) * BN * DHD; \
        const __nv_bfloat16* vs = vb + (size_t)(tile) * BN * DHD; \
        uint32_t kB = smb + SM_KV(buf), vB = kB + 8192; \
        _Pragma("unroll") \
        for (int i = 0; i < 4; i++) { \
            int c = t + i * 128; int r = c >> 3; int cb = (c & 7) * 16; \
            uint32_t d = SWZ(r * 128, cb); \
            cpasync16(kB + d, (const char*)ks + r * 128 + cb); \
            cpasync16(vB + d, (const char*)vs + r * 128 + cb); \
        } \
    } while (0)

    PREFETCH(t0, 0); CP_COMMIT();
    __syncthreads();   // Q staged & visible

    // ---- load Q A-fragments (held for whole sweep) ----
    const int g = lane >> 3, lr = lane & 7;
    uint32_t qa[4][4];
    {
        const int row = wid * 16 + (g & 1) * 8 + lr;
        #pragma unroll
        for (int ks = 0; ks < 4; ks++) {
            uint32_t a = smb + SM_Q + SWZ(row * 128, ks * 32 + (g >> 1) * 16);
            ldm_x4(qa[ks], a);
        }
    }

    float o[8][4];
    #pragma unroll
    for (int j = 0; j < 8; j++)
        #pragma unroll
        for (int i = 0; i < 4; i++) o[j][i] = 0.f;
    float ls0 = 0.f, ls1 = 0.f;

    for (int it = 0; it < TILES_PER_SPLIT; it++) {
        const int buf = it & 1;
        if (it + 1 < TILES_PER_SPLIT) {
            PREFETCH(t0 + it + 1, buf ^ 1); CP_COMMIT();
            asm volatile("cp.async.wait_group 1;" ::: "memory");
        } else {
            asm volatile("cp.async.wait_group 0;" ::: "memory");
        }
        __syncthreads();   // tile's buffer visible to all warps

        const uint32_t kB = smb + SM_KV(buf), vB = kB + 8192;

        // ---- S = Q K^T : 8 n-tiles x 4 k-steps ----
        float s[8][4];
        #pragma unroll
        for (int j = 0; j < 8; j++)
            #pragma unroll
            for (int i = 0; i < 4; i++) s[j][i] = 0.f;

        #pragma unroll
        for (int ks = 0; ks < 4; ks++) {
            uint32_t kf[4][4];
            #pragma unroll
            for (int p = 0; p < 4; p++) {
                int row = p * 16 + (g >> 1) * 8 + lr;
                uint32_t a = kB + SWZ(row * 128, ks * 32 + (g & 1) * 16);
                ldm_x4(kf[p], a);
            }
            #pragma unroll
            for (int j = 0; j < 8; j++) {
                int p = j >> 1, off = (j & 1) * 2;
                mma16816(s[j], qa[ks], kf[p][off], kf[p][off + 1]);
            }
        }

        // ---- softmax: p = exp2(s) (bounded; no max), pack into A-frags ----
        uint32_t pf[4][4];
        #pragma unroll
        for (int k2 = 0; k2 < 4; k2++) {
            float e00 = ex2f(s[2 * k2][0]),     e01 = ex2f(s[2 * k2][1]);
            float e02 = ex2f(s[2 * k2][2]),     e03 = ex2f(s[2 * k2][3]);
            float e10 = ex2f(s[2 * k2 + 1][0]), e11 = ex2f(s[2 * k2 + 1][1]);
            float e12 = ex2f(s[2 * k2 + 1][2]), e13 = ex2f(s[2 * k2 + 1][3]);
            ls0 += (e00 + e01) + (e10 + e11);
            ls1 += (e02 + e03) + (e12 + e13);
            pf[k2][0] = pk_bf16x2(e00, e01);
            pf[k2][1] = pk_bf16x2(e02, e03);
            pf[k2][2] = pk_bf16x2(e10, e11);
            pf[k2][3] = pk_bf16x2(e12, e13);
        }

        // ---- O += P V : ldmatrix.trans on natural V[kv][dh] ----
        #pragma unroll
        for (int k2 = 0; k2 < 4; k2++) {
            uint32_t vf[4][4];
            #pragma unroll
            for (int p = 0; p < 4; p++) {
                int row = k2 * 16 + (g & 1) * 8 + lr;
                ldm_x4t(vf[p], vB + SWZ(row * 128, (2 * p + (g >> 1)) * 16));
            }
            #pragma unroll
            for (int j = 0; j < 8; j++) {
                int p = j >> 1, off = (j & 1) * 2;
                mma16816(o[j], pf[k2], vf[p][off], vf[p][off + 1]);
            }
        }
        __syncthreads();   // all warps done with buf before it is refilled
    }

    // ---- reduce l across quad, write unnormalized partials ----
    ls0 += __shfl_xor_sync(0xffffffffu, ls0, 1);
    ls0 += __shfl_xor_sync(0xffffffffu, ls0, 2);
    ls1 += __shfl_xor_sync(0xffffffffu, ls1, 1);
    ls1 += __shfl_xor_sync(0xffffffffu, ls1, 2);

    const int r0 = q0 + wid * 16 + (lane >> 2);
    const int cbase = (lane & 3) * 2;
    const size_t rowbase = (size_t)(split * NB + b) * SEQ + r0;
    float* op0 = g_opart + rowbase * DHD;
    float* op1 = op0 + 8 * DHD;
    if ((lane & 3) == 0) {
        g_lpart[rowbase] = ls0;
        g_lpart[rowbase + 8] = ls1;
    }
    #pragma unroll
    for (int j = 0; j < 8; j++) {
        int c = 8 * j + cbase;
        *(float2*)(op0 + c) = make_float2(o[j][0], o[j][1]);
        *(float2*)(op1 + c) = make_float2(o[j][2], o[j][3]);
    }
}

// ---------------- reduce partials + fused epilogue ----------------
__global__ __launch_bounds__(256)
void reduce_ep(const float* __restrict__ q, float* __restrict__ out)
{
    const size_t i = (size_t)blockIdx.x * blockDim.x + threadIdx.x;  // float4 index
    const size_t half4 = (size_t)NB * SEQ * DHD / 4;
    float4 o0 = ((const float4*)g_opart)[i];
    float4 o1 = ((const float4*)g_opart)[i + half4];
    size_t row = i >> 4;                       // 16 float4 per row
    float l = g_lpart[row] + g_lpart[row + (size_t)NB * SEQ];
    float il = 1.0f / l;
    float4 qv = ((const float4*)q)[i];

    float x0 = (o0.x + o1.x) * il + qv.x;
    float x1 = (o0.y + o1.y) * il + qv.y;
    float x2 = (o0.z + o1.z) * il + qv.z;
    float x3 = (o0.w + o1.w) * il + qv.w;
    #pragma unroll
    for (int it = 0; it < 3; it++) {
        x0 = __fdividef(1.0f, 1.0f + __expf(-(x0 + 2.0f * qv.x)));
        x1 = __fdividef(1.0f, 1.0f + __expf(-(x1 + 2.0f * qv.y)));
        x2 = __fdividef(1.0f, 1.0f + __expf(-(x2 + 2.0f * qv.z)));
        x3 = __fdividef(1.0f, 1.0f + __expf(-(x3 + 2.0f * qv.w)));
    }
    ((float4*)out)[i] = make_float4(x0, x1, x2, x3);
}

extern "C" void kernel_launch(void* const* d_in, const int* in_sizes, int n_in,
                              void* d_out, int out_size)
{
    const float* q = (const float*)d_in[0];
    const float* k = (const float*)d_in[1];
    const float* v = (const float*)d_in[2];
    const int* scale_raw = (const int*)d_in[3];
    float* out = (float*)d_out;

    // prepass: K,V -> bf16 scratch
    const size_t n4 = (size_t)NB * SEQ * DHD / 4;
    cvt_kv<<<(unsigned)(n4 / 256), 256>>>((const float4*)k, (const float4*)v);

    cudaFuncSetAttribute(attn_mma, cudaFuncAttributeMaxDynamicSharedMemorySize, SM_TOTAL);
    dim3 grid(SEQ / BM, NB, NSPLIT);
    attn_mma<<<grid, NTHREADS, SM_TOTAL>>>(q, scale_raw);

    reduce_ep<<<(unsigned)(n4 / 256), 256>>>(q, out);
}

// round 16
// speedup vs baseline: 1.0268x; 1.0268x over previous
#include <cuda_runtime.h>
#include <cuda_bf16.h>
#include <cstdint>

#define SEQ 4096
#define NB 4
#define DHD 64
#define BM 64
#define BN 64
#define NTILES (SEQ / BN)
#define NTHREADS 128

// bf16 copies of K and V (filled by prepass kernel). 2 MB each.
__device__ __nv_bfloat16 g_kbf[(size_t)NB * SEQ * DHD];
__device__ __nv_bfloat16 g_vbf[(size_t)NB * SEQ * DHD];

// smem layout (bytes): Q[64][64]bf16 swizzled (8KB) | {K,V} x 3 buffers (16KB each)
#define SM_Q 0
#define SM_KV(buf) (8192 + (buf) * 16384)   // K at +0 (8KB), V at +8192 (8KB)
#define SM_TOTAL (8192 + 3 * 16384)         // 57344

// XOR swizzle inside a 128B row: 16B-chunk column ^ (row & 7)
#define SWZ(rowbyte, colbyte) ((rowbyte) + ((colbyte) ^ (((rowbyte) >> 7 & 7) << 4)))

// ---------------- helpers ----------------
__device__ __forceinline__ uint32_t smem_u32(const void* p) {
    uint32_t a;
    asm("{ .reg .u64 t; cvta.to.shared.u64 t, %1; cvt.u32.u64 %0, t; }" : "=r"(a) : "l"(p));
    return a;
}
__device__ __forceinline__ uint32_t pk_bf16x2(float lo, float hi) {
    uint32_t r;
    asm("cvt.rn.bf16x2.f32 %0, %1, %2;" : "=r"(r) : "f"(hi), "f"(lo));
    return r;
}
__device__ __forceinline__ float ex2f(float x) {
    float r; asm("ex2.approx.ftz.f32 %0, %1;" : "=f"(r) : "f"(x)); return r;
}
__device__ __forceinline__ void cpasync16(uint32_t dst, const void* src) {
    asm volatile("cp.async.cg.shared.global [%0], [%1], 16;" :: "r"(dst), "l"(src) : "memory");
}
#define CP_COMMIT() asm volatile("cp.async.commit_group;" ::: "memory")

__device__ __forceinline__ void ldm_x4(uint32_t* r, uint32_t a) {
    asm volatile("ldmatrix.sync.aligned.m8n8.x4.shared.b16 {%0,%1,%2,%3}, [%4];"
        : "=r"(r[0]), "=r"(r[1]), "=r"(r[2]), "=r"(r[3]) : "r"(a));
}
__device__ __forceinline__ void ldm_x4t(uint32_t* r, uint32_t a) {
    asm volatile("ldmatrix.sync.aligned.m8n8.x4.trans.shared.b16 {%0,%1,%2,%3}, [%4];"
        : "=r"(r[0]), "=r"(r[1]), "=r"(r[2]), "=r"(r[3]) : "r"(a));
}
__device__ __forceinline__ void mma16816(float* d, const uint32_t* a, uint32_t b0, uint32_t b1) {
    asm volatile("mma.sync.aligned.m16n8k16.row.col.f32.bf16.bf16.f32 "
        "{%0,%1,%2,%3}, {%4,%5,%6,%7}, {%8,%9}, {%0,%1,%2,%3};"
        : "+f"(d[0]), "+f"(d[1]), "+f"(d[2]), "+f"(d[3])
        : "r"(a[0]), "r"(a[1]), "r"(a[2]), "r"(a[3]), "r"(b0), "r"(b1));
}

// ---------------- prepass: fp32 -> bf16 for K and V ----------------
__global__ __launch_bounds__(256)
void cvt_kv(const float4* __restrict__ k, const float4* __restrict__ v)
{
    size_t i = (size_t)blockIdx.x * blockDim.x + threadIdx.x;   // over N/4
    float4 a = k[i];
    ((uint2*)g_kbf)[i] = make_uint2(pk_bf16x2(a.x, a.y), pk_bf16x2(a.z, a.w));
    float4 b = v[i];
    ((uint2*)g_vbf)[i] = make_uint2(pk_bf16x2(b.x, b.y), pk_bf16x2(b.z, b.w));
}

// ---------------- main kernel ----------------
__global__ __launch_bounds__(NTHREADS, 2)
void attn_mma(const float* __restrict__ q, const int* __restrict__ scale_raw,
              float* __restrict__ out)
{
    extern __shared__ char smc[];
    const uint32_t smb = smem_u32(smc);
    const int t = threadIdx.x;
    const int wid = t >> 5;
    const int lane = t & 31;
    const int b = blockIdx.y;
    const int q0 = blockIdx.x * BM;

    int raw = *scale_raw;
    float inv_scale = (raw >= 0 && raw < (1 << 23)) ? (float)raw : __int_as_float(raw);
    const float qf = 1.4426950408889634f / inv_scale;   // fold 1/scale and log2(e)

    const float* qb = q + ((size_t)b * SEQ + q0) * DHD;
    const __nv_bfloat16* kb = g_kbf + (size_t)b * SEQ * DHD;
    const __nv_bfloat16* vb = g_vbf + (size_t)b * SEQ * DHD;

    // ---- stage Q (bf16, prescaled, swizzled): 64 rows x 64 cols ----
    {
        const int r = t >> 1, h = t & 1;
        const float4* src = (const float4*)(qb + (size_t)r * DHD + h * 32);
        #pragma unroll
        for (int c = 0; c < 4; c++) {
            float4 x0 = src[2 * c], x1 = src[2 * c + 1];
            uint32_t p0 = pk_bf16x2(x0.x * qf, x0.y * qf);
            uint32_t p1 = pk_bf16x2(x0.z * qf, x0.w * qf);
            uint32_t p2 = pk_bf16x2(x1.x * qf, x1.y * qf);
            uint32_t p3 = pk_bf16x2(x1.z * qf, x1.w * qf);
            uint32_t a = smb + SM_Q + SWZ(r * 128, h * 64 + c * 16);
            asm volatile("st.shared.v4.b32 [%0], {%1,%2,%3,%4};"
                :: "r"(a), "r"(p0), "r"(p1), "r"(p2), "r"(p3) : "memory");
        }
    }

    // ---- K/V tile prefetch (512 x 16B chunks per tensor, 128 threads x 4) ----
    #define PREFETCH(tile, buf) do { \
        const __nv_bfloat16* ks = kb + (size_t)(tile) * BN * DHD; \
        const __nv_bfloat16* vs = vb + (size_t)(tile) * BN * DHD; \
        uint32_t kB = smb + SM_KV(buf), vB = kB + 8192; \
        _Pragma("unroll") \
        for (int i = 0; i < 4; i++) { \
            int c = t + i * 128; int r = c >> 3; int cb = (c & 7) * 16; \
            uint32_t d = SWZ(r * 128, cb); \
            cpasync16(kB + d, (const char*)ks + r * 128 + cb); \
            cpasync16(vB + d, (const char*)vs + r * 128 + cb); \
        } \
    } while (0)

    PREFETCH(0, 0); CP_COMMIT();
    PREFETCH(1, 1); CP_COMMIT();
    asm volatile("cp.async.wait_group 1;" ::: "memory");  // tile 0 arrived
    __syncthreads();   // Q + tile 0 visible

    // ---- load Q A-fragments (held for whole sweep) ----
    const int g = lane >> 3, lr = lane & 7;
    uint32_t qa[4][4];
    {
        const int row = wid * 16 + (g & 1) * 8 + lr;
        #pragma unroll
        for (int ks = 0; ks < 4; ks++) {
            uint32_t a = smb + SM_Q + SWZ(row * 128, ks * 32 + (g >> 1) * 16);
            ldm_x4(qa[ks], a);
        }
    }

    float o[8][4];
    #pragma unroll
    for (int j = 0; j < 8; j++)
        #pragma unroll
        for (int i = 0; i < 4; i++) o[j][i] = 0.f;
    float ls0 = 0.f, ls1 = 0.f;
    float s[8][4];
    uint32_t pf[4][4];   // P fragments for the "current" tile (A-operand of PV)

    // ---- compute S for a tile's K buffer into s ----
    #define S_COMPUTE(kB) do { \
        _Pragma("unroll") \
        for (int j = 0; j < 8; j++) \
            _Pragma("unroll") \
            for (int i = 0; i < 4; i++) s[j][i] = 0.f; \
        _Pragma("unroll") \
        for (int ks = 0; ks < 4; ks++) { \
            uint32_t kf[4][4]; \
            _Pragma("unroll") \
            for (int p = 0; p < 4; p++) { \
                int row = p * 16 + (g >> 1) * 8 + lr; \
                ldm_x4(kf[p], (kB) + SWZ(row * 128, ks * 32 + (g & 1) * 16)); \
            } \
            _Pragma("unroll") \
            for (int j = 0; j < 8; j++) { \
                int p = j >> 1, off = (j & 1) * 2; \
                mma16816(s[j], qa[ks], kf[p][off], kf[p][off + 1]); \
            } \
        } \
    } while (0)

    // ---- exp s -> pf[k2] (one k2 step) ----
    #define EXP_STEP(k2) do { \
        float e00 = ex2f(s[2 * (k2)][0]),     e01 = ex2f(s[2 * (k2)][1]); \
        float e02 = ex2f(s[2 * (k2)][2]),     e03 = ex2f(s[2 * (k2)][3]); \
        float e10 = ex2f(s[2 * (k2) + 1][0]), e11 = ex2f(s[2 * (k2) + 1][1]); \
        float e12 = ex2f(s[2 * (k2) + 1][2]), e13 = ex2f(s[2 * (k2) + 1][3]); \
        ls0 += (e00 + e01) + (e10 + e11); \
        ls1 += (e02 + e03) + (e12 + e13); \
        pf[k2][0] = pk_bf16x2(e00, e01); \
        pf[k2][1] = pk_bf16x2(e02, e03); \
        pf[k2][2] = pk_bf16x2(e10, e11); \
        pf[k2][3] = pk_bf16x2(e12, e13); \
    } while (0)

    // ---- prologue: S_0, exp_0 ----
    S_COMPUTE(smb + SM_KV(0));
    #pragma unroll
    for (int k2 = 0; k2 < 4; k2++) EXP_STEP(k2);

    // ---- pipelined main loop: iter it computes S_{it+1}, PV_it, exp_{it+1} ----
    for (int it = 0; it < NTILES - 1; it++) {
        __syncthreads();   // all warps done with iter it-1 (frees buf (it+2)%3)
        if (it + 2 < NTILES) {
            PREFETCH(it + 2, (it + 2) % 3); CP_COMMIT();
            asm volatile("cp.async.wait_group 1;" ::: "memory");  // tile it+1 arrived
        } else {
            asm volatile("cp.async.wait_group 0;" ::: "memory");
        }
        __syncthreads();   // visibility of tile it+1

        const uint32_t kB = smb + SM_KV((it + 1) % 3);          // K_{it+1}
        const uint32_t vB = smb + SM_KV(it % 3) + 8192;         // V_{it}

        S_COMPUTE(kB);   // s = S_{it+1}

        // PV_it interleaved with exp_{it+1}: per k2, MMAs consume pf[k2]
        // (tile it), then pf[k2] is overwritten with exp of tile it+1.
        #pragma unroll
        for (int k2 = 0; k2 < 4; k2++) {
            uint32_t vf[4][4];
            #pragma unroll
            for (int p = 0; p < 4; p++) {
                int row = k2 * 16 + (g & 1) * 8 + lr;
                ldm_x4t(vf[p], vB + SWZ(row * 128, (2 * p + (g >> 1)) * 16));
            }
            #pragma unroll
            for (int j = 0; j < 8; j++) {
                int p = j >> 1, off = (j & 1) * 2;
                mma16816(o[j], pf[k2], vf[p][off], vf[p][off + 1]);
            }
            EXP_STEP(k2);   // MUFU work hides under the MMA issue stream
        }
    }

    // ---- epilogue: PV_{last} ----
    {
        const uint32_t vB = smb + SM_KV((NTILES - 1) % 3) + 8192;
        #pragma unroll
        for (int k2 = 0; k2 < 4; k2++) {
            uint32_t vf[4][4];
            #pragma unroll
            for (int p = 0; p < 4; p++) {
                int row = k2 * 16 + (g & 1) * 8 + lr;
                ldm_x4t(vf[p], vB + SWZ(row * 128, (2 * p + (g >> 1)) * 16));
            }
            #pragma unroll
            for (int j = 0; j < 8; j++) {
                int p = j >> 1, off = (j & 1) * 2;
                mma16816(o[j], pf[k2], vf[p][off], vf[p][off + 1]);
            }
        }
    }

    // ---- reduce l across quad (lanes sharing a row) ----
    ls0 += __shfl_xor_sync(0xffffffffu, ls0, 1);
    ls0 += __shfl_xor_sync(0xffffffffu, ls0, 2);
    ls1 += __shfl_xor_sync(0xffffffffu, ls1, 1);
    ls1 += __shfl_xor_sync(0xffffffffu, ls1, 2);
    const float il0 = 1.0f / ls0, il1 = 1.0f / ls1;

    // ---- epilogue: x = o/l + q, then 3x sigmoid(x + 2q); clamp no-op ----
    const int r0 = q0 + wid * 16 + (lane >> 2);
    const int cbase = (lane & 3) * 2;
    const float* qr0 = q + ((size_t)b * SEQ + r0) * DHD;
    const float* qr1 = qr0 + 8 * DHD;
    float* or0 = out + ((size_t)b * SEQ + r0) * DHD;
    float* or1 = or0 + 8 * DHD;
    #pragma unroll
    for (int j = 0; j < 8; j++) {
        int c = 8 * j + cbase;
        float2 q0v = *(const float2*)(qr0 + c);
        float2 q1v = *(const float2*)(qr1 + c);
        float x0 = o[j][0] * il0 + q0v.x, x1 = o[j][1] * il0 + q0v.y;
        float x2 = o[j][2] * il1 + q1v.x, x3 = o[j][3] * il1 + q1v.y;
        #pragma unroll
        for (int it = 0; it < 3; it++) {
            x0 = __fdividef(1.0f, 1.0f + __expf(-(x0 + 2.0f * q0v.x)));
            x1 = __fdividef(1.0f, 1.0f + __expf(-(x1 + 2.0f * q0v.y)));
            x2 = __fdividef(1.0f, 1.0f + __expf(-(x2 + 2.0f * q1v.x)));
            x3 = __fdividef(1.0f, 1.0f + __expf(-(x3 + 2.0f * q1v.y)));
        }
        *(float2*)(or0 + c) = make_float2(x0, x1);
        *(float2*)(or1 + c) = make_float2(x2, x3);
    }
}

extern "C" void kernel_launch(void* const* d_in, const int* in_sizes, int n_in,
                              void* d_out, int out_size)
{
    const float* q = (const float*)d_in[0];
    const float* k = (const float*)d_in[1];
    const float* v = (const float*)d_in[2];
    const int* scale_raw = (const int*)d_in[3];
    float* out = (float*)d_out;

    // prepass: K,V -> bf16 scratch
    const size_t n4 = (size_t)NB * SEQ * DHD / 4;
    cvt_kv<<<(unsigned)(n4 / 256), 256>>>((const float4*)k, (const float4*)v);

    cudaFuncSetAttribute(attn_mma, cudaFuncAttributeMaxDynamicSharedMemorySize, SM_TOTAL);
    dim3 grid(SEQ / BM, NB);
    attn_mma<<<grid, NTHREADS, SM_TOTAL>>>(q, scale_raw, out);
}

// round 17
// speedup vs baseline: 1.0284x; 1.0016x over previous
#include <cuda_runtime.h>
#include <cuda_bf16.h>
#include <cstdint>

#define SEQ 4096
#define NB 4
#define DHD 64
#define BM 64
#define BN 64
#define NTILES (SEQ / BN)
#define NTHREADS 256

// bf16 copies of K and V (filled by prepass kernel). 2 MB each.
__device__ __nv_bfloat16 g_kbf[(size_t)NB * SEQ * DHD];
__device__ __nv_bfloat16 g_vbf[(size_t)NB * SEQ * DHD];

// smem layout (bytes): Q[64][64]bf16 swizzled (8KB) | {K,V} x 2 buffers (16KB each)
#define SM_Q 0
#define SM_KV(buf) (8192 + (buf) * 16384)   // K at +0 (8KB), V at +8192 (8KB)
#define SM_TOTAL (8192 + 2 * 16384)         // 40960
// end-of-kernel reduction scratch (reuses KV buffer 0 region):
#define SM_RED_L 8192                       // 64 floats
#define SM_RED_O 8448                       // 64 rows x stride 66 floats

// XOR swizzle inside a 128B row: 16B-chunk column ^ (row & 7)
#define SWZ(rowbyte, colbyte) ((rowbyte) + ((colbyte) ^ (((rowbyte) >> 7 & 7) << 4)))

// ---------------- helpers ----------------
__device__ __forceinline__ uint32_t smem_u32(const void* p) {
    uint32_t a;
    asm("{ .reg .u64 t; cvta.to.shared.u64 t, %1; cvt.u32.u64 %0, t; }" : "=r"(a) : "l"(p));
    return a;
}
__device__ __forceinline__ uint32_t pk_bf16x2(float lo, float hi) {
    uint32_t r;
    asm("cvt.rn.bf16x2.f32 %0, %1, %2;" : "=r"(r) : "f"(hi), "f"(lo));
    return r;
}
__device__ __forceinline__ float ex2f(float x) {
    float r; asm("ex2.approx.ftz.f32 %0, %1;" : "=f"(r) : "f"(x)); return r;
}
__device__ __forceinline__ void cpasync16(uint32_t dst, const void* src) {
    asm volatile("cp.async.cg.shared.global [%0], [%1], 16;" :: "r"(dst), "l"(src) : "memory");
}
#define CP_COMMIT() asm volatile("cp.async.commit_group;" ::: "memory")

__device__ __forceinline__ void ldm_x4(uint32_t* r, uint32_t a) {
    asm volatile("ldmatrix.sync.aligned.m8n8.x4.shared.b16 {%0,%1,%2,%3}, [%4];"
        : "=r"(r[0]), "=r"(r[1]), "=r"(r[2]), "=r"(r[3]) : "r"(a));
}
__device__ __forceinline__ void ldm_x4t(uint32_t* r, uint32_t a) {
    asm volatile("ldmatrix.sync.aligned.m8n8.x4.trans.shared.b16 {%0,%1,%2,%3}, [%4];"
        : "=r"(r[0]), "=r"(r[1]), "=r"(r[2]), "=r"(r[3]) : "r"(a));
}
__device__ __forceinline__ void mma16816(float* d, const uint32_t* a, uint32_t b0, uint32_t b1) {
    asm volatile("mma.sync.aligned.m16n8k16.row.col.f32.bf16.bf16.f32 "
        "{%0,%1,%2,%3}, {%4,%5,%6,%7}, {%8,%9}, {%0,%1,%2,%3};"
        : "+f"(d[0]), "+f"(d[1]), "+f"(d[2]), "+f"(d[3])
        : "r"(a[0]), "r"(a[1]), "r"(a[2]), "r"(a[3]), "r"(b0), "r"(b1));
}

// ---------------- prepass: fp32 -> bf16 for K and V ----------------
__global__ __launch_bounds__(256)
void cvt_kv(const float4* __restrict__ k, const float4* __restrict__ v)
{
    size_t i = (size_t)blockIdx.x * blockDim.x + threadIdx.x;   // over N/4
    float4 a = k[i];
    ((uint2*)g_kbf)[i] = make_uint2(pk_bf16x2(a.x, a.y), pk_bf16x2(a.z, a.w));
    float4 b = v[i];
    ((uint2*)g_vbf)[i] = make_uint2(pk_bf16x2(b.x, b.y), pk_bf16x2(b.z, b.w));
}

// ---------------- main kernel: warp-split-KV flash attention ----------------
__global__ __launch_bounds__(NTHREADS, 2)
void attn_mma(const float* __restrict__ q, const int* __restrict__ scale_raw,
              float* __restrict__ out)
{
    extern __shared__ char smc[];
    const uint32_t smb = smem_u32(smc);
    const int t = threadIdx.x;
    const int wid = t >> 5;
    const int lane = t & 31;
    const int mrow = wid & 3;       // q-row group: rows mrow*16 .. +15
    const int khalf = wid >> 2;     // kv half within each tile: khalf*32 .. +31
    const int b = blockIdx.y;
    const int q0 = blockIdx.x * BM;

    int raw = *scale_raw;
    float inv_scale = (raw >= 0 && raw < (1 << 23)) ? (float)raw : __int_as_float(raw);
    const float qf = 1.4426950408889634f / inv_scale;   // fold 1/scale and log2(e)

    const float* qb = q + ((size_t)b * SEQ + q0) * DHD;
    const __nv_bfloat16* kb = g_kbf + (size_t)b * SEQ * DHD;
    const __nv_bfloat16* vb = g_vbf + (size_t)b * SEQ * DHD;

    // ---- stage Q (bf16, prescaled, swizzled): 64 rows x 64 cols ----
    {
        const int r = t >> 2, qtr = t & 3;   // 16 cols per thread
        const float4* src = (const float4*)(qb + (size_t)r * DHD + qtr * 16);
        #pragma unroll
        for (int c = 0; c < 2; c++) {
            float4 x0 = src[2 * c], x1 = src[2 * c + 1];
            uint32_t p0 = pk_bf16x2(x0.x * qf, x0.y * qf);
            uint32_t p1 = pk_bf16x2(x0.z * qf, x0.w * qf);
            uint32_t p2 = pk_bf16x2(x1.x * qf, x1.y * qf);
            uint32_t p3 = pk_bf16x2(x1.z * qf, x1.w * qf);
            uint32_t a = smb + SM_Q + SWZ(r * 128, qtr * 32 + c * 16);
            asm volatile("st.shared.v4.b32 [%0], {%1,%2,%3,%4};"
                :: "r"(a), "r"(p0), "r"(p1), "r"(p2), "r"(p3) : "memory");
        }
    }

    // ---- K/V tile prefetch (512 x 16B chunks per tensor, 256 threads x 2) ----
    #define PREFETCH(tile, buf) do { \
        const __nv_bfloat16* ks = kb + (size_t)(tile) * BN * DHD; \
        const __nv_bfloat16* vs = vb + (size_t)(tile) * BN * DHD; \
        uint32_t kB = smb + SM_KV(buf), vB = kB + 8192; \
        _Pragma("unroll") \
        for (int i = 0; i < 2; i++) { \
            int c = t + i * 256; int r = c >> 3; int cb = (c & 7) * 16; \
            uint32_t d = SWZ(r * 128, cb); \
            cpasync16(kB + d, (const char*)ks + r * 128 + cb); \
            cpasync16(vB + d, (const char*)vs + r * 128 + cb); \
        } \
    } while (0)

    PREFETCH(0, 0); CP_COMMIT();
    __syncthreads();   // Q staged & visible

    // ---- load Q A-fragments (held for whole sweep) ----
    const int g = lane >> 3, lr = lane & 7;
    uint32_t qa[4][4];
    {
        const int row = mrow * 16 + (g & 1) * 8 + lr;
        #pragma unroll
        for (int ks = 0; ks < 4; ks++) {
            uint32_t a = smb + SM_Q + SWZ(row * 128, ks * 32 + (g >> 1) * 16);
            ldm_x4(qa[ks], a);
        }
    }

    float o[8][4];
    #pragma unroll
    for (int j = 0; j < 8; j++)
        #pragma unroll
        for (int i = 0; i < 4; i++) o[j][i] = 0.f;
    float ls0 = 0.f, ls1 = 0.f;

    for (int it = 0; it < NTILES; it++) {
        const int buf = it & 1;
        if (it + 1 < NTILES) {
            PREFETCH(it + 1, buf ^ 1); CP_COMMIT();
            asm volatile("cp.async.wait_group 1;" ::: "memory");
        } else {
            asm volatile("cp.async.wait_group 0;" ::: "memory");
        }
        __syncthreads();   // tile's buffer visible to all warps

        const uint32_t kB = smb + SM_KV(buf), vB = kB + 8192;

        // ---- S = Q K_half^T : 4 n-tiles (32 kv) x 4 k-steps ----
        float s[4][4];
        #pragma unroll
        for (int j = 0; j < 4; j++)
            #pragma unroll
            for (int i = 0; i < 4; i++) s[j][i] = 0.f;

        #pragma unroll
        for (int ks = 0; ks < 4; ks++) {
            uint32_t kf[2][4];
            #pragma unroll
            for (int p = 0; p < 2; p++) {
                int row = khalf * 32 + p * 16 + (g >> 1) * 8 + lr;
                ldm_x4(kf[p], kB + SWZ(row * 128, ks * 32 + (g & 1) * 16));
            }
            #pragma unroll
            for (int j = 0; j < 4; j++) {
                int p = j >> 1, off = (j & 1) * 2;
                mma16816(s[j], qa[ks], kf[p][off], kf[p][off + 1]);
            }
        }

        // ---- softmax: p = exp2(s) (bounded; no max), pack into A-frags ----
        uint32_t pf[2][4];
        #pragma unroll
        for (int k2 = 0; k2 < 2; k2++) {
            float e00 = ex2f(s[2 * k2][0]),     e01 = ex2f(s[2 * k2][1]);
            float e02 = ex2f(s[2 * k2][2]),     e03 = ex2f(s[2 * k2][3]);
            float e10 = ex2f(s[2 * k2 + 1][0]), e11 = ex2f(s[2 * k2 + 1][1]);
            float e12 = ex2f(s[2 * k2 + 1][2]), e13 = ex2f(s[2 * k2 + 1][3]);
            ls0 += (e00 + e01) + (e10 + e11);
            ls1 += (e02 + e03) + (e12 + e13);
            pf[k2][0] = pk_bf16x2(e00, e01);
            pf[k2][1] = pk_bf16x2(e02, e03);
            pf[k2][2] = pk_bf16x2(e10, e11);
            pf[k2][3] = pk_bf16x2(e12, e13);
        }

        // ---- O += P V_half : ldmatrix.trans on natural V[kv][dh] ----
        #pragma unroll
        for (int k2 = 0; k2 < 2; k2++) {
            uint32_t vf[4][4];
            #pragma unroll
            for (int p = 0; p < 4; p++) {
                int row = khalf * 32 + k2 * 16 + (g & 1) * 8 + lr;
                ldm_x4t(vf[p], vB + SWZ(row * 128, (2 * p + (g >> 1)) * 16));
            }
            #pragma unroll
            for (int j = 0; j < 8; j++) {
                int p = j >> 1, off = (j & 1) * 2;
                mma16816(o[j], pf[k2], vf[p][off], vf[p][off + 1]);
            }
        }
        __syncthreads();   // all warps done with buf before it is refilled
    }

    // ---- reduce l across quad (lanes sharing a row) ----
    ls0 += __shfl_xor_sync(0xffffffffu, ls0, 1);
    ls0 += __shfl_xor_sync(0xffffffffu, ls0, 2);
    ls1 += __shfl_xor_sync(0xffffffffu, ls1, 1);
    ls1 += __shfl_xor_sync(0xffffffffu, ls1, 2);

    // ---- cross-warp-pair reduction (kv halves) via smem ----
    __syncthreads();   // KV buffers dead; safe to reuse for reduction
    float* Lred = (float*)(smc + SM_RED_L);
    float* Ored = (float*)(smc + SM_RED_O);
    const int rr = lane >> 2, cc = (lane & 3) * 2;
    if (khalf == 1) {
        if ((lane & 3) == 0) {
            Lred[mrow * 16 + rr] = ls0;
            Lred[mrow * 16 + rr + 8] = ls1;
        }
        #pragma unroll
        for (int j = 0; j < 8; j++) {
            int c = 8 * j + cc;
            *(float2*)&Ored[(mrow * 16 + rr) * 66 + c]     = make_float2(o[j][0], o[j][1]);
            *(float2*)&Ored[(mrow * 16 + rr + 8) * 66 + c] = make_float2(o[j][2], o[j][3]);
        }
    }
    __syncthreads();

    if (khalf == 0) {
        ls0 += Lred[mrow * 16 + rr];
        ls1 += Lred[mrow * 16 + rr + 8];
        const float il0 = 1.0f / ls0, il1 = 1.0f / ls1;

        const int r0 = q0 + mrow * 16 + rr;
        const float* qr0 = q + ((size_t)b * SEQ + r0) * DHD;
        const float* qr1 = qr0 + 8 * DHD;
        float* or0 = out + ((size_t)b * SEQ + r0) * DHD;
        float* or1 = or0 + 8 * DHD;
        #pragma unroll
        for (int j = 0; j < 8; j++) {
            int c = 8 * j + cc;
            float2 h0 = *(float2*)&Ored[(mrow * 16 + rr) * 66 + c];
            float2 h1 = *(float2*)&Ored[(mrow * 16 + rr + 8) * 66 + c];
            float2 q0v = *(const float2*)(qr0 + c);
            float2 q1v = *(const float2*)(qr1 + c);
            float x0 = (o[j][0] + h0.x) * il0 + q0v.x;
            float x1 = (o[j][1] + h0.y) * il0 + q0v.y;
            float x2 = (o[j][2] + h1.x) * il1 + q1v.x;
            float x3 = (o[j][3] + h1.y) * il1 + q1v.y;
            #pragma unroll
            for (int s3 = 0; s3 < 3; s3++) {
                x0 = __fdividef(1.0f, 1.0f + __expf(-(x0 + 2.0f * q0v.x)));
                x1 = __fdividef(1.0f, 1.0f + __expf(-(x1 + 2.0f * q0v.y)));
                x2 = __fdividef(1.0f, 1.0f + __expf(-(x2 + 2.0f * q1v.x)));
                x3 = __fdividef(1.0f, 1.0f + __expf(-(x3 + 2.0f * q1v.y)));
            }
            *(float2*)(or0 + c) = make_float2(x0, x1);
            *(float2*)(or1 + c) = make_float2(x2, x3);
        }
    }
}

extern "C" void kernel_launch(void* const* d_in, const int* in_sizes, int n_in,
                              void* d_out, int out_size)
{
    const float* q = (const float*)d_in[0];
    const float* k = (const float*)d_in[1];
    const float* v = (const float*)d_in[2];
    const int* scale_raw = (const int*)d_in[3];
    float* out = (float*)d_out;

    // prepass: K,V -> bf16 scratch
    const size_t n4 = (size_t)NB * SEQ * DHD / 4;
    cvt_kv<<<(unsigned)(n4 / 256), 256>>>((const float4*)k, (const float4*)v);

    cudaFuncSetAttribute(attn_mma, cudaFuncAttributeMaxDynamicSharedMemorySize, SM_TOTAL);
    dim3 grid(SEQ / BM, NB);
    attn_mma<<<grid, NTHREADS, SM_TOTAL>>>(q, scale_raw, out);
}